// round 16
// baseline (speedup 1.0000x reference)
#include <cuda_runtime.h>
#include <math.h>

// ---------------- problem constants ----------------
#define MAXN 10000
#define MAXE 160000

// ---------------- scratch ----------------
__device__ float g_Xni[MAXN * 256];
__device__ float g_Xnt[MAXN * 64];
__device__ float g_Pi [MAXN * 256];
__device__ float g_Pj [MAXN * 256];
__device__ float g_scores[MAXE * 4];
__device__ float g_ex  [MAXE * 4];
__device__ float g_smax[MAXN * 4];
__device__ float g_den [MAXN * 4];
__device__ float g_agg [MAXN * 256];
__device__ float g_deg [MAXN];
__device__ float g_NM0 [MAXN * 64];
__device__ float g_NM1 [MAXN * 64];
__device__ float g_nodeout[MAXN * 64];
__device__ float g_xg  [MAXN * 64];
// A1/A2/Comb in MMA-fragment layout; Em*/Et row-major [N,K]; node weights row-major [N,K]
__device__ float g_BtA1  [256 * 256];
__device__ float g_BtA2  [256 * 256];
__device__ float g_BtComb[256 * 128];
__device__ float g_BtEm0 [64 * 256];
__device__ float g_BtEm1 [64 * 64];
__device__ float g_BtEm2 [64 * 64];
__device__ float g_BtEt  [64 * 128];
__device__ float g_BtNi  [256 * 256];
__device__ float g_BtFold[256 * 256];
__device__ float g_BtPj  [256 * 256];

static __device__ __forceinline__ float to_tf32(float x) {
    float r; asm("cvt.rna.tf32.f32 %0, %1;" : "=f"(r) : "f"(x)); return r;
}
static __device__ __forceinline__ void mma_tf32(float* d, const unsigned* a, const unsigned* b) {
    asm volatile(
        "mma.sync.aligned.m16n8k8.row.col.f32.tf32.tf32.f32 "
        "{%0,%1,%2,%3}, {%4,%5,%6,%7}, {%8,%9}, {%0,%1,%2,%3};"
        : "+f"(d[0]), "+f"(d[1]), "+f"(d[2]), "+f"(d[3])
        : "r"(a[0]), "r"(a[1]), "r"(a[2]), "r"(a[3]), "r"(b[0]), "r"(b[1]));
}
static __device__ __forceinline__ unsigned smem_u32(const void* p) {
    unsigned a;
    asm("{ .reg .u64 t; cvta.to.shared.u64 t, %1; cvt.u32.u64 %0, t; }" : "=r"(a) : "l"(p));
    return a;
}
static __device__ __forceinline__ void cpa16(unsigned dst, const float* src) {
    asm volatile("cp.async.ca.shared.global [%0], [%1], 16;" :: "r"(dst), "l"(src));
}
static __device__ __forceinline__ void atomicAdd4(float4* a, float4 v) {
#if !defined(__CUDA_ARCH__) || __CUDA_ARCH__ >= 900
    atomicAdd(a, v);
#else
    atomicAdd(&a->x, v.x); atomicAdd(&a->y, v.y);
    atomicAdd(&a->z, v.z); atomicAdd(&a->w, v.w);
#endif
}
__device__ __forceinline__ void atomicMaxFloat(float* addr, float v)
{
    if (v >= 0.0f) atomicMax(reinterpret_cast<int*>(addr), __float_as_int(v));
    else           atomicMin(reinterpret_cast<unsigned int*>(addr), __float_as_uint(v));
}

// fragment position for weight element (k input-dim, n output-dim), Nd = total outputs
static __device__ __forceinline__ int frag_pos(int k, int n, int Nd) {
    int chunk = k >> 4, kin = k & 15;
    return ((chunk * (Nd >> 3) + (n >> 3)) * 32 + (n & 7) * 4 + (kin & 3)) * 4
           + ((kin >> 3) * 2 + ((kin >> 2) & 1));
}

// ---------------- frag-layout gemm stage (validated on Nd=256 stages) ----------------
template<int NF>
static __device__ __forceinline__ void gemm_stage_fr(
    const float* __restrict__ sA, const float* __restrict__ BtF, int K,
    float* __restrict__ sW, unsigned sWu, int tid, float (&acc)[NF][4])
{
    constexpr int NTOT = NF * 16;
    constexpr int CHUNK_F4 = NTOT * 4;
    const int lane = tid & 31, wid = tid >> 5;
    const int wm = wid & 7, wn = wid >> 3;
    const int lq = lane >> 2, lc = lane & 3;
    const int NC = K >> 4;

#pragma unroll
    for (int j = 0; j < NF; j++)
#pragma unroll
        for (int q = 0; q < 4; q++) acc[j][q] = 0.f;

    for (int i = tid; i < CHUNK_F4; i += 512)
        cpa16(sWu + (unsigned)i * 16u, BtF + (size_t)i * 4);
    asm volatile("cp.async.commit_group;");

    for (int c = 0; c < NC; c++) {
        if (c + 1 < NC) {
            unsigned boff = (unsigned)(((c + 1) & 1) * NTOT * 16) * 4u;
            const float* gsrc = BtF + (size_t)(c + 1) * NTOT * 16;
            for (int i = tid; i < CHUNK_F4; i += 512)
                cpa16(sWu + boff + (unsigned)i * 16u, gsrc + (size_t)i * 4);
            asm volatile("cp.async.commit_group;");
            asm volatile("cp.async.wait_group 1;");
        } else {
            asm volatile("cp.async.wait_group 0;");
        }
        __syncthreads();
        const float4* B = reinterpret_cast<const float4*>(sW + (c & 1) * NTOT * 16);
        const int kb = c * 16;
        unsigned a0[4], a8[4];
        {
            int m = wm * 16 + lq;
            a0[0] = __float_as_uint(sA[m * 260 + kb + lc]);
            a0[1] = __float_as_uint(sA[(m + 8) * 260 + kb + lc]);
            a0[2] = __float_as_uint(sA[m * 260 + kb + 4 + lc]);
            a0[3] = __float_as_uint(sA[(m + 8) * 260 + kb + 4 + lc]);
            a8[0] = __float_as_uint(sA[m * 260 + kb + 8 + lc]);
            a8[1] = __float_as_uint(sA[(m + 8) * 260 + kb + 8 + lc]);
            a8[2] = __float_as_uint(sA[m * 260 + kb + 12 + lc]);
            a8[3] = __float_as_uint(sA[(m + 8) * 260 + kb + 12 + lc]);
        }
#pragma unroll
        for (int nf = 0; nf < NF; nf++) {
            float4 bv = B[(wn * NF + nf) * 32 + lane];
            unsigned b[2];
            b[0] = __float_as_uint(bv.x); b[1] = __float_as_uint(bv.y);
            mma_tf32(acc[nf], a0, b);
            b[0] = __float_as_uint(bv.z); b[1] = __float_as_uint(bv.w);
            mma_tf32(acc[nf], a8, b);
        }
        __syncthreads();
    }
}

// ---------------- row-major gemm stage (R13-proven; used for Nd=64 stages) ----------------
template<int NF>
static __device__ __forceinline__ void gemm_stage_rm(
    const float* __restrict__ sA, const float* __restrict__ Bt, int K,
    float* __restrict__ sW, unsigned sWu, int tid, float (&acc)[NF][4])
{
    constexpr int NTOT = NF * 16;
    const int lane = tid & 31, wid = tid >> 5;
    const int wm = wid & 7, wn = wid >> 3;
    const int lq = lane >> 2, lc = lane & 3;
    const int NC = K >> 4;

#pragma unroll
    for (int j = 0; j < NF; j++)
#pragma unroll
        for (int q = 0; q < 4; q++) acc[j][q] = 0.f;

    for (int i = tid; i < NTOT * 4; i += 512) {
        int n = i >> 2, q = i & 3;
        cpa16(sWu + (unsigned)(n * 20 + q * 4) * 4u, Bt + (size_t)n * K + q * 4);
    }
    asm volatile("cp.async.commit_group;");

    for (int c = 0; c < NC; c++) {
        if (c + 1 < NC) {
            unsigned boff = (unsigned)(((c + 1) & 1) * NTOT * 20) * 4u;
            for (int i = tid; i < NTOT * 4; i += 512) {
                int n = i >> 2, q = i & 3;
                cpa16(sWu + boff + (unsigned)(n * 20 + q * 4) * 4u,
                      Bt + (size_t)n * K + (c + 1) * 16 + q * 4);
            }
            asm volatile("cp.async.commit_group;");
            asm volatile("cp.async.wait_group 1;");
        } else {
            asm volatile("cp.async.wait_group 0;");
        }
        __syncthreads();
        const float* B = sW + (c & 1) * NTOT * 20;
        const int kb = c * 16;
#pragma unroll
        for (int kk = 0; kk < 16; kk += 8) {
            unsigned a[4];
            int m = wm * 16 + lq;
            a[0] = __float_as_uint(sA[m * 260 + kb + kk + lc]);
            a[1] = __float_as_uint(sA[(m + 8) * 260 + kb + kk + lc]);
            a[2] = __float_as_uint(sA[m * 260 + kb + kk + 4 + lc]);
            a[3] = __float_as_uint(sA[(m + 8) * 260 + kb + kk + 4 + lc]);
#pragma unroll
            for (int nf = 0; nf < NF; nf++) {
                unsigned b[2];
                int n = wn * (NF * 8) + nf * 8 + lq;
                b[0] = __float_as_uint(B[n * 20 + kk + lc]);
                b[1] = __float_as_uint(B[n * 20 + kk + 4 + lc]);
                mma_tf32(acc[nf], a, b);
            }
        }
        __syncthreads();
    }
}

// ---------------- fused edge mega-kernel (128-edge tiles, in-place, 512 thr) ----------------
__global__ void __launch_bounds__(512)
edge_fused(const float* __restrict__ edge, const int* __restrict__ src,
           const int* __restrict__ dst, int E,
           const float* __restrict__ A0_b, const float* __restrict__ A1_b,
           const float* __restrict__ A2_b, const float* __restrict__ Em0_b,
           const float* __restrict__ Em1_b, const float* __restrict__ Em2_b,
           const float* __restrict__ b_et,
           const float* __restrict__ attn, float* __restrict__ out_edge)
{
    extern __shared__ float sm[];
    float* sA  = sm;             // 128*260 = 33280
    float* sW  = sm + 33280;     // 8192 (frag: 2*4096; rm NF=4: 2*1280)
    float* sEt = sm + 41472;     // 128*66 = 8448
    float* sSc = sm + 49920;     // 512
    int*   sS  = (int*)(sm + 50432);   // 128
    int*   sD  = (int*)(sm + 50560);   // 128
    const unsigned sWu = smem_u32(sW);

    const int tid = threadIdx.x;
    const int e0 = blockIdx.x * 128;
    const int lane = tid & 31, wid = tid >> 5;
    const int wm = wid & 7, wn = wid >> 3;
    const int lq = lane >> 2, lc = lane & 3;

    if (tid < 128) {
        int e = min(e0 + tid, E - 1);
        sS[tid] = src[e]; sD[tid] = dst[e];
    }
    for (int i = tid; i < 128 * 32; i += 512) {
        int r = i >> 5, q = i & 31;
        float4 v = make_float4(0.f, 0.f, 0.f, 0.f);
        if (e0 + r < E) v = *(const float4*)(edge + (size_t)(e0 + r) * 128 + q * 4);
        v.x = to_tf32(v.x); v.y = to_tf32(v.y); v.z = to_tf32(v.z); v.w = to_tf32(v.w);
        *(float4*)(sA + r * 260 + q * 4) = v;
    }
    __syncthreads();

    // ---- stage Et: sEt = edge@W_et + b_et ----
    {
        float acc[4][4];
        gemm_stage_rm<4>(sA, g_BtEt, 128, sW, sWu, tid, acc);
#pragma unroll
        for (int nf = 0; nf < 4; nf++) {
            int col = wn * 32 + nf * 8 + lc * 2;
            float2 bb = *(const float2*)(b_et + col);
#pragma unroll
            for (int h = 0; h < 2; h++) {
                int r = wm * 16 + h * 8 + lq;
                sEt[r * 66 + col]     = acc[nf][h*2+0] + bb.x;
                sEt[r * 66 + col + 1] = acc[nf][h*2+1] + bb.y;
            }
        }
    }

    // ---- stage 0: sA = relu(edge@Wcomb + Pi[dst] + Pj[src] + A0_b) ----
    {
        float acc[16][4];
        gemm_stage_fr<16>(sA, g_BtComb, 128, sW, sWu, tid, acc);
#pragma unroll
        for (int nf = 0; nf < 16; nf++) {
            int col = wn * 128 + nf * 8 + lc * 2;
            float2 bb = *(const float2*)(A0_b + col);
#pragma unroll
            for (int h = 0; h < 2; h++) {
                int r = wm * 16 + h * 8 + lq;
                int d = sD[r], s = sS[r];
                float2 pi = *(const float2*)(g_Pi + (size_t)d * 256 + col);
                float2 pj = *(const float2*)(g_Pj + (size_t)s * 256 + col);
                sA[r * 260 + col]     = to_tf32(fmaxf(acc[nf][h*2+0] + pi.x + pj.x + bb.x, 0.f));
                sA[r * 260 + col + 1] = to_tf32(fmaxf(acc[nf][h*2+1] + pi.y + pj.y + bb.y, 0.f));
            }
        }
    }
    __syncthreads();

    // ---- stage 1: sA = relu(sA@A1 + b1) ----
    {
        float acc[16][4];
        gemm_stage_fr<16>(sA, g_BtA1, 256, sW, sWu, tid, acc);
#pragma unroll
        for (int nf = 0; nf < 16; nf++) {
            int col = wn * 128 + nf * 8 + lc * 2;
            float2 bb = *(const float2*)(A1_b + col);
#pragma unroll
            for (int h = 0; h < 2; h++) {
                int r = wm * 16 + h * 8 + lq;
                sA[r * 260 + col]     = to_tf32(fmaxf(acc[nf][h*2+0] + bb.x, 0.f));
                sA[r * 260 + col + 1] = to_tf32(fmaxf(acc[nf][h*2+1] + bb.y, 0.f));
            }
        }
    }
    __syncthreads();

    // ---- stage 2: sA = relu(sA@A2 + b2), fused attention scores ----
    {
        float acc[16][4];
        gemm_stage_fr<16>(sA, g_BtA2, 256, sW, sWu, tid, acc);
        float sp[2][2] = {{0.f, 0.f}, {0.f, 0.f}};
#pragma unroll
        for (int nf = 0; nf < 16; nf++) {
            int col = wn * 128 + nf * 8 + lc * 2;
            float2 bb = *(const float2*)(A2_b + col);
            float2 av = *(const float2*)(attn + col);
#pragma unroll
            for (int h = 0; h < 2; h++) {
                int r = wm * 16 + h * 8 + lq;
                float v0 = fmaxf(acc[nf][h*2+0] + bb.x, 0.f);
                float v1 = fmaxf(acc[nf][h*2+1] + bb.y, 0.f);
                sA[r * 260 + col]     = to_tf32(v0);
                sA[r * 260 + col + 1] = to_tf32(v1);
                sp[h][nf >> 3] += v0 * av.x + v1 * av.y;
            }
        }
#pragma unroll
        for (int h = 0; h < 2; h++)
#pragma unroll
            for (int g = 0; g < 2; g++) {
                float v = sp[h][g];
                v += __shfl_xor_sync(0xffffffffu, v, 1);
                v += __shfl_xor_sync(0xffffffffu, v, 2);
                if (lc == 0)
                    sSc[(wm * 16 + h * 8 + lq) * 4 + wn * 2 + g] = v;
            }
    }
    __syncthreads();

    // ---- stage 3: sA(cols 0..63) = relu(sA@Em0 + b) ----
    {
        float acc[4][4];
        gemm_stage_rm<4>(sA, g_BtEm0, 256, sW, sWu, tid, acc);
#pragma unroll
        for (int nf = 0; nf < 4; nf++) {
            int col = wn * 32 + nf * 8 + lc * 2;
            float2 bb = *(const float2*)(Em0_b + col);
#pragma unroll
            for (int h = 0; h < 2; h++) {
                int r = wm * 16 + h * 8 + lq;
                sA[r * 260 + col]     = to_tf32(fmaxf(acc[nf][h*2+0] + bb.x, 0.f));
                sA[r * 260 + col + 1] = to_tf32(fmaxf(acc[nf][h*2+1] + bb.y, 0.f));
            }
        }
    }
    __syncthreads();

    // ---- stage 4: sA(cols 0..63) = relu(sA@Em1 + b) ----
    {
        float acc[4][4];
        gemm_stage_rm<4>(sA, g_BtEm1, 64, sW, sWu, tid, acc);
#pragma unroll
        for (int nf = 0; nf < 4; nf++) {
            int col = wn * 32 + nf * 8 + lc * 2;
            float2 bb = *(const float2*)(Em1_b + col);
#pragma unroll
            for (int h = 0; h < 2; h++) {
                int r = wm * 16 + h * 8 + lq;
                sA[r * 260 + col]     = to_tf32(fmaxf(acc[nf][h*2+0] + bb.x, 0.f));
                sA[r * 260 + col + 1] = to_tf32(fmaxf(acc[nf][h*2+1] + bb.y, 0.f));
            }
        }
    }
    __syncthreads();

    // ---- stage 5: out_edge = relu(sA@Em2 + b) + Et ----
    {
        float acc[4][4];
        gemm_stage_rm<4>(sA, g_BtEm2, 64, sW, sWu, tid, acc);
#pragma unroll
        for (int nf = 0; nf < 4; nf++) {
            int col = wn * 32 + nf * 8 + lc * 2;
            float2 bb = *(const float2*)(Em2_b + col);
#pragma unroll
            for (int h = 0; h < 2; h++) {
                int r = wm * 16 + h * 8 + lq;
                if (e0 + r < E) {
                    float2 o;
                    o.x = fmaxf(acc[nf][h*2+0] + bb.x, 0.f) + sEt[r * 66 + col];
                    o.y = fmaxf(acc[nf][h*2+1] + bb.y, 0.f) + sEt[r * 66 + col + 1];
                    *(float2*)(out_edge + (size_t)(e0 + r) * 64 + col) = o;
                }
            }
        }
    }
    __syncthreads();

    // ---- scores + segment max + degree ----
    {
        int r = tid >> 2, h = tid & 3;
        if (e0 + r < E) {
            float v = sSc[tid];
            g_scores[(size_t)(e0 + r) * 4 + h] = v;
            atomicMaxFloat(&g_smax[(size_t)sD[r] * 4 + h], v);
        }
    }
    if (tid < 128 && e0 + tid < E && sS[tid] != sD[tid])
        atomicAdd(&g_deg[sS[tid]], 1.0f);
}

// ---------------- tf32 warp-MMA GEMM body (node-level, 256 thr, row-major Bt) ----------------
static __device__ __forceinline__ void mma128_body(
    const float* __restrict__ A, const float* __restrict__ Bt,
    float* __restrict__ C, int M, int K, int ldc, int m0, int n0)
{
    __shared__ float As[128][20];
    __shared__ float Bs[128][20];

    const int tid = threadIdx.x;
    const int lane = tid & 31, wid = tid >> 5;
    const int wm = wid & 3, wn = wid >> 2;
    const int lq = lane >> 2;
    const int lc = lane & 3;

    float acc[2][8][4];
#pragma unroll
    for (int i = 0; i < 2; i++)
#pragma unroll
        for (int j = 0; j < 8; j++)
#pragma unroll
            for (int q = 0; q < 4; q++) acc[i][j][q] = 0.0f;

    for (int k0 = 0; k0 < K; k0 += 16) {
#pragma unroll
        for (int i = tid; i < 512; i += 256) {
            int m = i >> 2, q = i & 3;
            float4 v = make_float4(0.f, 0.f, 0.f, 0.f);
            int row = m0 + m;
            if (row < M) v = *reinterpret_cast<const float4*>(A + (size_t)row * K + k0 + q * 4);
            v.x = to_tf32(v.x); v.y = to_tf32(v.y); v.z = to_tf32(v.z); v.w = to_tf32(v.w);
            *reinterpret_cast<float4*>(&As[m][q * 4]) = v;
        }
#pragma unroll
        for (int i = tid; i < 512; i += 256) {
            int n = i >> 2, q = i & 3;
            float4 v = *reinterpret_cast<const float4*>(Bt + (size_t)(n0 + n) * K + k0 + q * 4);
            *reinterpret_cast<float4*>(&Bs[n][q * 4]) = v;
        }
        __syncthreads();

#pragma unroll
        for (int kk = 0; kk < 16; kk += 8) {
            unsigned a[2][4];
#pragma unroll
            for (int mf = 0; mf < 2; mf++) {
                int m = wm * 32 + mf * 16 + lq;
                a[mf][0] = __float_as_uint(As[m][kk + lc]);
                a[mf][1] = __float_as_uint(As[m + 8][kk + lc]);
                a[mf][2] = __float_as_uint(As[m][kk + 4 + lc]);
                a[mf][3] = __float_as_uint(As[m + 8][kk + 4 + lc]);
            }
            unsigned b[8][2];
#pragma unroll
            for (int nf = 0; nf < 8; nf++) {
                int n = wn * 64 + nf * 8 + lq;
                b[nf][0] = __float_as_uint(Bs[n][kk + lc]);
                b[nf][1] = __float_as_uint(Bs[n][kk + 4 + lc]);
            }
#pragma unroll
            for (int mf = 0; mf < 2; mf++)
#pragma unroll
                for (int nf = 0; nf < 8; nf++)
                    mma_tf32(acc[mf][nf], a[mf], b[nf]);
        }
        __syncthreads();
    }

#pragma unroll
    for (int mf = 0; mf < 2; mf++) {
#pragma unroll
        for (int nf = 0; nf < 8; nf++) {
            int row = m0 + wm * 32 + mf * 16 + lq;
            int col = n0 + wn * 64 + nf * 8 + lc * 2;
            float2 v0 = make_float2(acc[mf][nf][0], acc[mf][nf][1]);
            float2 v1 = make_float2(acc[mf][nf][2], acc[mf][nf][3]);
            if (row < M)
                *reinterpret_cast<float2*>(C + (size_t)row * ldc + col) = v0;
            if (row + 8 < M)
                *reinterpret_cast<float2*>(C + (size_t)(row + 8) * ldc + col) = v1;
        }
    }
}

__global__ void __launch_bounds__(256)
mma_node3(const float* __restrict__ A,
          const float* __restrict__ B0, const float* __restrict__ B1, const float* __restrict__ B2,
          float* __restrict__ C0, float* __restrict__ C1, float* __restrict__ C2, int M)
{
    int z = blockIdx.z;
    const float* Bt = (z == 0) ? B0 : (z == 1) ? B1 : B2;
    float* C = (z == 0) ? C0 : (z == 1) ? C1 : C2;
    mma128_body(A, Bt, C, M, 256, 256, blockIdx.x * 128, blockIdx.y * 128);
}

// ---------------- prep: folds + weight transposes (frag or row-major) ----------------
struct PrepTable {
    const float* W[7];
    float* Bt[7];
    int K[7];
    int Nd[7];
    int frag[7];
};
__global__ void __launch_bounds__(256)
prep(const float* __restrict__ W_nj, const float* __restrict__ W_eij,
     const float* __restrict__ W_ni, const float* __restrict__ A0_W, PrepTable tab)
{
    int z = blockIdx.z;
    if (z >= 3) {
        int s = z - 3;
        const float* W = tab.W[s];
        float* Bt = tab.Bt[s];
        int K = tab.K[s], Nd = tab.Nd[s], fr = tab.frag[s];
        int total = K * Nd;
        int bid = blockIdx.y * 2 + blockIdx.x;
        for (int i = bid * 256 + threadIdx.x; i < total; i += 4 * 256) {
            int k = i / Nd, n = i % Nd;
            float v = to_tf32(W[i]);
            if (fr) Bt[frag_pos(k, n, Nd)] = v;
            else    Bt[(size_t)n * K + k] = v;
        }
        return;
    }
    // fold GEMM
    const float* A; const float* W; float* Bt; int M; int Kdim; int fr;
    if (z == 0)      { A = W_nj;  W = A0_W;             Bt = g_BtFold; M = 256; Kdim = 256; fr = 0; }
    else if (z == 1) { A = W_eij; W = A0_W + 256 * 256; Bt = g_BtComb; M = 128; Kdim = 128; fr = 1; }
    else             { A = W_ni;  W = A0_W + 512 * 256; Bt = g_BtPj;   M = 256; Kdim = 256; fr = 0; }
    const int m0 = blockIdx.x * 128;
    const int n0 = blockIdx.y * 128;
    if (m0 >= M) return;

    __shared__ float As[16][132];
    __shared__ float Ws[16][128];
    const int tid = threadIdx.x;
    const int tx = tid & 15, ty = tid >> 4;

    float acc[8][8];
#pragma unroll
    for (int i = 0; i < 8; i++)
#pragma unroll
        for (int j = 0; j < 8; j++) acc[i][j] = 0.0f;

    for (int k0 = 0; k0 < 256; k0 += 16) {
#pragma unroll
        for (int i = tid; i < 512; i += 256) {
            int m = i >> 2, k4 = i & 3;
            float4 v = *reinterpret_cast<const float4*>(A + (size_t)(m0 + m) * 256 + k0 + k4 * 4);
            As[k4 * 4 + 0][m] = v.x;
            As[k4 * 4 + 1][m] = v.y;
            As[k4 * 4 + 2][m] = v.z;
            As[k4 * 4 + 3][m] = v.w;
        }
#pragma unroll
        for (int i = tid; i < 512; i += 256) {
            int k = i >> 5, n4 = i & 31;
            *reinterpret_cast<float4*>(&Ws[k][n4 * 4]) =
                *reinterpret_cast<const float4*>(W + (size_t)(k0 + k) * 256 + n0 + n4 * 4);
        }
        __syncthreads();
#pragma unroll
        for (int k = 0; k < 16; k++) {
            float a[8], b[8];
#pragma unroll
            for (int i = 0; i < 8; i++) a[i] = As[k][ty * 8 + i];
#pragma unroll
            for (int j = 0; j < 8; j++) b[j] = Ws[k][tx * 8 + j];
#pragma unroll
            for (int i = 0; i < 8; i++)
#pragma unroll
                for (int j = 0; j < 8; j++)
                    acc[i][j] = fmaf(a[i], b[j], acc[i][j]);
        }
        __syncthreads();
    }
#pragma unroll
    for (int i = 0; i < 8; i++) {
        int krow = m0 + ty * 8 + i;
#pragma unroll
        for (int j = 0; j < 8; j++) {
            int ncol = n0 + tx * 8 + j;
            float v = to_tf32(acc[i][j]);
            if (fr) Bt[frag_pos(krow, ncol, 256)] = v;
            else    Bt[(size_t)ncol * Kdim + krow] = v;
        }
    }
}

// ---------------- generic tiled fp32 SGEMM ----------------
template<int BM, int BN, int BK, int TM, int TN, bool RELU, bool BIAS, bool RES>
__global__ void __launch_bounds__((BM / TM) * (BN / TN))
sgemm(const float* __restrict__ A, int lda,
      const float* __restrict__ W,
      const float* __restrict__ bias,
      const float* __restrict__ res, int ldres,
      float* __restrict__ C, int ldc,
      int M, int N, int K)
{
    constexpr int NT = (BM / TM) * (BN / TN);
    __shared__ float As[BK][BM + 4];
    __shared__ float Ws[BK][BN];

    const int tid = threadIdx.x;
    const int tx = tid % (BN / TN);
    const int ty = tid / (BN / TN);
    const int m0 = blockIdx.x * BM;
    const int n0 = blockIdx.y * BN;

    float acc[TM][TN];
#pragma unroll
    for (int i = 0; i < TM; i++)
#pragma unroll
        for (int j = 0; j < TN; j++) acc[i][j] = 0.0f;

    for (int k0 = 0; k0 < K; k0 += BK) {
#pragma unroll
        for (int i = tid; i < BM * BK / 4; i += NT) {
            int m  = i / (BK / 4);
            int k4 = i % (BK / 4);
            float4 v = make_float4(0.f, 0.f, 0.f, 0.f);
            int row = m0 + m;
            if (row < M)
                v = *reinterpret_cast<const float4*>(A + (size_t)row * lda + k0 + k4 * 4);
            As[k4 * 4 + 0][m] = v.x;
            As[k4 * 4 + 1][m] = v.y;
            As[k4 * 4 + 2][m] = v.z;
            As[k4 * 4 + 3][m] = v.w;
        }
#pragma unroll
        for (int i = tid; i < BK * BN / 4; i += NT) {
            int k  = i / (BN / 4);
            int n4 = i % (BN / 4);
            *reinterpret_cast<float4*>(&Ws[k][n4 * 4]) =
                *reinterpret_cast<const float4*>(W + (size_t)(k0 + k) * N + n0 + n4 * 4);
        }
        __syncthreads();

#pragma unroll
        for (int k = 0; k < BK; k++) {
            float a[TM], b[TN];
#pragma unroll
            for (int i = 0; i < TM; i++) a[i] = As[k][ty * TM + i];
#pragma unroll
            for (int j = 0; j < TN; j++) b[j] = Ws[k][tx * TN + j];
#pragma unroll
            for (int i = 0; i < TM; i++)
#pragma unroll
                for (int j = 0; j < TN; j++)
                    acc[i][j] = fmaf(a[i], b[j], acc[i][j]);
        }
        __syncthreads();
    }

#pragma unroll
    for (int i = 0; i < TM; i++) {
        int row = m0 + ty * TM + i;
        if (row >= M) continue;
#pragma unroll
        for (int j = 0; j < TN; j++) {
            int col = n0 + tx * TN + j;
            float v = acc[i][j];
            if (BIAS) v += bias[col];
            if (RELU) v = fmaxf(v, 0.0f);
            if (RES)  v += res[(size_t)row * ldres + col];
            C[(size_t)row * ldc + col] = v;
        }
    }
}

// ---------------- small kernels ----------------
__global__ void init_kernel(int N)
{
    int i = blockIdx.x * blockDim.x + threadIdx.x;
    if (i < N * 4) { g_smax[i] = -INFINITY; g_den[i] = 0.0f; }
    if (i < N * 256) g_agg[i] = 0.0f;
    if (i < N) g_deg[i] = 1.0f;
}

__global__ void ex_kernel(const int* __restrict__ dst, int E)
{
    int i = blockIdx.x * blockDim.x + threadIdx.x;
    if (i >= E * 4) return;
    int e = i >> 2, h = i & 3;
    int d = dst[e];
    float v = expf(g_scores[i] - g_smax[d * 4 + h]);
    g_ex[i] = v;
    atomicAdd(&g_den[d * 4 + h], v);
}

__global__ void agg_kernel(const int* __restrict__ src, const int* __restrict__ dst, int E,
                           const float* __restrict__ linW, float* __restrict__ attn_out)
{
    int idx = blockIdx.x * blockDim.x + threadIdx.x;
    int e = idx >> 6;
    int t = idx & 63;
    if (e >= E) return;
    int d = dst[e], s = src[e];
    int h = t >> 4;
    float alpha = g_ex[e * 4 + h] / g_den[(size_t)d * 4 + h];
    if (t == 0) {
        float aw = 0.0f;
#pragma unroll
        for (int hh = 0; hh < 4; hh++)
            aw += (g_ex[e * 4 + hh] / g_den[(size_t)d * 4 + hh]) * linW[hh];
        attn_out[e] = aw;
    }
    float4 xj = reinterpret_cast<const float4*>(g_Xni + (size_t)s * 256)[t];
    float4 m = make_float4(xj.x * alpha, xj.y * alpha, xj.z * alpha, xj.w * alpha);
    atomicAdd4(reinterpret_cast<float4*>(g_agg + (size_t)d * 256 + t * 4), m);
}

__global__ void outinit_kernel(const float* __restrict__ gcn_b, float* __restrict__ out, int N)
{
    int i = blockIdx.x * blockDim.x + threadIdx.x;
    if (i >= N * 64) return;
    int n = i >> 6;
    out[i] = gcn_b[i & 63] + g_xg[i] / g_deg[n];
}

__global__ void gcn_scatter_kernel(const int* __restrict__ src, const int* __restrict__ dst,
                                   int E, float* __restrict__ out)
{
    int idx = blockIdx.x * blockDim.x + threadIdx.x;
    int e = idx >> 4;
    int t = idx & 15;
    if (e >= E) return;
    int s = src[e], d = dst[e];
    if (s == d) return;
    float w = rsqrtf(g_deg[s]) * rsqrtf(g_deg[d]);
    float4 v = reinterpret_cast<const float4*>(g_xg + (size_t)s * 64)[t];
    float4 m = make_float4(v.x * w, v.y * w, v.z * w, v.w * w);
    atomicAdd4(reinterpret_cast<float4*>(out + (size_t)d * 64 + t * 4), m);
}

// ---------------- launch ----------------
extern "C" void kernel_launch(void* const* d_in, const int* in_sizes, int n_in,
                              void* d_out, int out_size)
{
    const float* node = (const float*)d_in[0];
    const float* edge = (const float*)d_in[1];
    const int*   ei   = (const int*)d_in[2];
    const float* W_ni = (const float*)d_in[3];
    const float* W_nj = (const float*)d_in[4];
    const float* W_eij= (const float*)d_in[5];
    const float* W_nt = (const float*)d_in[6];
    const float* b_nt = (const float*)d_in[7];
    const float* W_et = (const float*)d_in[8];
    const float* b_et = (const float*)d_in[9];
    const float* A0_W = (const float*)d_in[10];
    const float* A0_b = (const float*)d_in[11];
    const float* A1_W = (const float*)d_in[12];
    const float* A1_b = (const float*)d_in[13];
    const float* A2_W = (const float*)d_in[14];
    const float* A2_b = (const float*)d_in[15];
    const float* attn = (const float*)d_in[16];
    const float* Nm0_W= (const float*)d_in[17];
    const float* Nm0_b= (const float*)d_in[18];
    const float* Nm1_W= (const float*)d_in[19];
    const float* Nm1_b= (const float*)d_in[20];
    const float* Nm2_W= (const float*)d_in[21];
    const float* Nm2_b= (const float*)d_in[22];
    const float* Em0_W= (const float*)d_in[23];
    const float* Em0_b= (const float*)d_in[24];
    const float* Em1_W= (const float*)d_in[25];
    const float* Em1_b= (const float*)d_in[26];
    const float* Em2_W= (const float*)d_in[27];
    const float* Em2_b= (const float*)d_in[28];
    const float* linW = (const float*)d_in[29];
    const float* gcnW = (const float*)d_in[30];
    const float* gcnb = (const float*)d_in[31];

    const int N = in_sizes[0] / 256;
    const int E = in_sizes[2] / 2;
    const int* src = ei;
    const int* dst = ei + E;

    float* out      = (float*)d_out;
    float* out_node = out;
    float* out_edge = out + (size_t)N * 64;
    float* out_attn = out_edge + (size_t)E * 64;

    void* p;
    cudaGetSymbolAddress(&p, g_Xni);    float* pXni = (float*)p;
    cudaGetSymbolAddress(&p, g_Xnt);    float* pXnt = (float*)p;
    cudaGetSymbolAddress(&p, g_Pi);     float* pPi  = (float*)p;
    cudaGetSymbolAddress(&p, g_Pj);     float* pPj  = (float*)p;
    cudaGetSymbolAddress(&p, g_agg);    float* pAgg = (float*)p;
    cudaGetSymbolAddress(&p, g_NM0);    float* pNM0 = (float*)p;
    cudaGetSymbolAddress(&p, g_NM1);    float* pNM1 = (float*)p;
    cudaGetSymbolAddress(&p, g_nodeout); float* pNodeOut = (float*)p;
    cudaGetSymbolAddress(&p, g_xg);     float* pXg  = (float*)p;
    cudaGetSymbolAddress(&p, g_BtA1);   float* pBtA1 = (float*)p;
    cudaGetSymbolAddress(&p, g_BtA2);   float* pBtA2 = (float*)p;
    cudaGetSymbolAddress(&p, g_BtEm0);  float* pBtEm0 = (float*)p;
    cudaGetSymbolAddress(&p, g_BtEm1);  float* pBtEm1 = (float*)p;
    cudaGetSymbolAddress(&p, g_BtEm2);  float* pBtEm2 = (float*)p;
    cudaGetSymbolAddress(&p, g_BtEt);   float* pBtEt = (float*)p;
    cudaGetSymbolAddress(&p, g_BtNi);   float* pBtNi = (float*)p;
    cudaGetSymbolAddress(&p, g_BtFold); float* pBtFold = (float*)p;
    cudaGetSymbolAddress(&p, g_BtPj);   float* pBtPj = (float*)p;

    const int TPB = 256;
    const int MT_N = (N + 127) / 128;
    const int ET = (E + 127) / 128;
    const int FUSED_SMEM = 50688 * 4;             // 198 KB
    cudaFuncSetAttribute(edge_fused, cudaFuncAttributeMaxDynamicSharedMemorySize, FUSED_SMEM);

    // #1 init
    init_kernel<<<(N * 256 + TPB - 1) / TPB, TPB>>>(N);

    // #2 prep: folds + transposes (A1/A2/Comb -> fragment layout; rest row-major)
    {
        PrepTable tab;
        tab.W[0] = A1_W;  tab.Bt[0] = pBtA1;  tab.K[0] = 256; tab.Nd[0] = 256; tab.frag[0] = 1;
        tab.W[1] = A2_W;  tab.Bt[1] = pBtA2;  tab.K[1] = 256; tab.Nd[1] = 256; tab.frag[1] = 1;
        tab.W[2] = Em0_W; tab.Bt[2] = pBtEm0; tab.K[2] = 256; tab.Nd[2] = 64;  tab.frag[2] = 0;
        tab.W[3] = Em1_W; tab.Bt[3] = pBtEm1; tab.K[3] = 64;  tab.Nd[3] = 64;  tab.frag[3] = 0;
        tab.W[4] = Em2_W; tab.Bt[4] = pBtEm2; tab.K[4] = 64;  tab.Nd[4] = 64;  tab.frag[4] = 0;
        tab.W[5] = W_et;  tab.Bt[5] = pBtEt;  tab.K[5] = 128; tab.Nd[5] = 64;  tab.frag[5] = 0;
        tab.W[6] = W_ni;  tab.Bt[6] = pBtNi;  tab.K[6] = 256; tab.Nd[6] = 256; tab.frag[6] = 0;
        dim3 g(2, 2, 10);
        prep<<<g, 256>>>(W_nj, W_eij, W_ni, A0_W, tab);
    }

    // #3 node projections batched: Xni / Pi / Pj
    {
        dim3 g(MT_N, 2, 3);
        mma_node3<<<g, 256>>>(node, pBtNi, pBtFold, pBtPj, pXni, pPi, pPj, N);
    }

    // #4 fused edge chain (profiled position)
    edge_fused<<<ET, 512, FUSED_SMEM>>>(edge, src, dst, E, A0_b, A1_b, A2_b,
                                        Em0_b, Em1_b, Em2_b, b_et, attn, out_edge);

    // #5 Xnt (fp32)
    {
        dim3 g(MT_N, 1);
        sgemm<128,64,16,8,4,false,true,false><<<g, 256>>>(node, 256, W_nt, b_nt, nullptr, 0, pXnt, 64, N, 64, 256);
    }

    // #6 softmax denominators
    ex_kernel<<<((size_t)E * 4 + TPB - 1) / TPB, TPB>>>(dst, E);

    // #7 message aggregation + attn weights
    agg_kernel<<<((size_t)E * 64 + TPB - 1) / TPB, TPB>>>(src, dst, E, linW, out_attn);

    // #8-11 node MLP + xg
    {
        dim3 g(MT_N, 1);
        sgemm<128,64,16,8,4,true,true,false><<<g, 256>>>(pAgg, 256, Nm0_W, Nm0_b, nullptr, 0, pNM0, 64, N, 64, 256);
        sgemm<128,64,16,8,4,true,true,false><<<g, 256>>>(pNM0, 64, Nm1_W, Nm1_b, nullptr, 0, pNM1, 64, N, 64, 64);
        sgemm<128,64,16,8,4,true,true,true><<<g, 256>>>(pNM1, 64, Nm2_W, Nm2_b, pXnt, 64, pNodeOut, 64, N, 64, 64);
        sgemm<128,64,16,8,4,false,false,false><<<g, 256>>>(pNodeOut, 64, gcnW, nullptr, nullptr, 0, pXg, 64, N, 64, 64);
    }

    // #12 out_node init
    outinit_kernel<<<(N * 64 + TPB - 1) / TPB, TPB>>>(gcnb, out_node, N);

    // #13 GCN scatter
    gcn_scatter_kernel<<<((size_t)E * 16 + TPB - 1) / TPB, TPB>>>(src, dst, E, out_node);
}

// round 17
// speedup vs baseline: 1.1038x; 1.1038x over previous
#include <cuda_runtime.h>
#include <math.h>

// ---------------- problem constants ----------------
#define MAXN 10000
#define MAXE 160000

// ---------------- scratch ----------------
__device__ float g_Xni[MAXN * 256];
__device__ float g_Xnt[MAXN * 64];
__device__ float g_Pi [MAXN * 256];
__device__ float g_Pj [MAXN * 256];
__device__ float g_scores[MAXE * 4];
__device__ float g_ex  [MAXE * 4];
__device__ float g_smax[MAXN * 4];
__device__ float g_den [MAXN * 4];
__device__ float g_agg [MAXN * 256];
__device__ float g_deg [MAXN];
__device__ float g_NM0 [MAXN * 64];
__device__ float g_NM1 [MAXN * 64];
__device__ float g_nodeout[MAXN * 64];
__device__ float g_xg  [MAXN * 64];
// transposed tf32 weights [N,K] (K contiguous)
__device__ float g_BtA1  [256 * 256];
__device__ float g_BtA2  [256 * 256];
__device__ float g_BtComb[256 * 128];
__device__ float g_BtEm0 [64 * 256];
__device__ float g_BtEm1 [64 * 64];
__device__ float g_BtEm2 [64 * 64];
__device__ float g_BtEt  [64 * 128];
__device__ float g_BtNi  [256 * 256];
__device__ float g_BtFold[256 * 256];
__device__ float g_BtPj  [256 * 256];

static __device__ __forceinline__ float to_tf32(float x) {
    float r; asm("cvt.rna.tf32.f32 %0, %1;" : "=f"(r) : "f"(x)); return r;
}
static __device__ __forceinline__ void mma_tf32(float* d, const unsigned* a, const unsigned* b) {
    asm volatile(
        "mma.sync.aligned.m16n8k8.row.col.f32.tf32.tf32.f32 "
        "{%0,%1,%2,%3}, {%4,%5,%6,%7}, {%8,%9}, {%0,%1,%2,%3};"
        : "+f"(d[0]), "+f"(d[1]), "+f"(d[2]), "+f"(d[3])
        : "r"(a[0]), "r"(a[1]), "r"(a[2]), "r"(a[3]), "r"(b[0]), "r"(b[1]));
}
static __device__ __forceinline__ unsigned smem_u32(const void* p) {
    unsigned a;
    asm("{ .reg .u64 t; cvta.to.shared.u64 t, %1; cvt.u32.u64 %0, t; }" : "=r"(a) : "l"(p));
    return a;
}
static __device__ __forceinline__ void cpa16(unsigned dst, const float* src) {
    asm volatile("cp.async.ca.shared.global [%0], [%1], 16;" :: "r"(dst), "l"(src));
}
static __device__ __forceinline__ void atomicAdd4(float4* a, float4 v) {
#if !defined(__CUDA_ARCH__) || __CUDA_ARCH__ >= 900
    atomicAdd(a, v);
#else
    atomicAdd(&a->x, v.x); atomicAdd(&a->y, v.y);
    atomicAdd(&a->z, v.z); atomicAdd(&a->w, v.w);
#endif
}
__device__ __forceinline__ void atomicMaxFloat(float* addr, float v)
{
    if (v >= 0.0f) atomicMax(reinterpret_cast<int*>(addr), __float_as_int(v));
    else           atomicMin(reinterpret_cast<unsigned int*>(addr), __float_as_uint(v));
}

// ---------------- fused edge-chain building block (512 thr, 4x4 warp grid) ----------------
// Warp (wm = wid&3, wn = wid>>2): rows wm*32..+31 (2 mf), cols wn*(NF*8)..(NF frags).
// Nd = NF*32. acc[2][NF][4]. Weights row-major [Nd,K], double-buffered 16-K chunks.
template<int NF>
static __device__ __forceinline__ void gemm_stage(
    const float* __restrict__ sA, const float* __restrict__ Bt, int K,
    float* __restrict__ sW, unsigned sWu, int tid, float (&acc)[2][NF][4])
{
    constexpr int NTOT = NF * 32;
    const int lane = tid & 31, wid = tid >> 5;
    const int wm = wid & 3, wn = wid >> 2;
    const int lq = lane >> 2, lc = lane & 3;
    const int NC = K >> 4;

#pragma unroll
    for (int i = 0; i < 2; i++)
#pragma unroll
        for (int j = 0; j < NF; j++)
#pragma unroll
            for (int q = 0; q < 4; q++) acc[i][j][q] = 0.f;

    for (int i = tid; i < NTOT * 4; i += 512) {
        int n = i >> 2, q = i & 3;
        cpa16(sWu + (unsigned)(n * 20 + q * 4) * 4u, Bt + (size_t)n * K + q * 4);
    }
    asm volatile("cp.async.commit_group;");

    for (int c = 0; c < NC; c++) {
        if (c + 1 < NC) {
            unsigned boff = (unsigned)(((c + 1) & 1) * NTOT * 20) * 4u;
            for (int i = tid; i < NTOT * 4; i += 512) {
                int n = i >> 2, q = i & 3;
                cpa16(sWu + boff + (unsigned)(n * 20 + q * 4) * 4u,
                      Bt + (size_t)n * K + (c + 1) * 16 + q * 4);
            }
            asm volatile("cp.async.commit_group;");
            asm volatile("cp.async.wait_group 1;");
        } else {
            asm volatile("cp.async.wait_group 0;");
        }
        __syncthreads();
        const float* B = sW + (c & 1) * NTOT * 20;
        const int kb = c * 16;
#pragma unroll
        for (int kk = 0; kk < 16; kk += 8) {
            unsigned a[2][4];
#pragma unroll
            for (int mf = 0; mf < 2; mf++) {
                int m = wm * 32 + mf * 16 + lq;
                a[mf][0] = __float_as_uint(sA[m * 260 + kb + kk + lc]);
                a[mf][1] = __float_as_uint(sA[(m + 8) * 260 + kb + kk + lc]);
                a[mf][2] = __float_as_uint(sA[m * 260 + kb + kk + 4 + lc]);
                a[mf][3] = __float_as_uint(sA[(m + 8) * 260 + kb + kk + 4 + lc]);
            }
#pragma unroll
            for (int nf = 0; nf < NF; nf++) {
                unsigned b[2];
                int n = wn * (NF * 8) + nf * 8 + lq;
                b[0] = __float_as_uint(B[n * 20 + kk + lc]);
                b[1] = __float_as_uint(B[n * 20 + kk + 4 + lc]);
                mma_tf32(acc[0][nf], a[0], b);
                mma_tf32(acc[1][nf], a[1], b);
            }
        }
        __syncthreads();
    }
}

// ---------------- fused edge mega-kernel (128-edge tiles, in-place, 512 thr) ----------------
__global__ void __launch_bounds__(512)
edge_fused(const float* __restrict__ edge, const int* __restrict__ src,
           const int* __restrict__ dst, int E,
           const float* __restrict__ A0_b, const float* __restrict__ A1_b,
           const float* __restrict__ A2_b, const float* __restrict__ Em0_b,
           const float* __restrict__ Em1_b, const float* __restrict__ Em2_b,
           const float* __restrict__ b_et,
           const float* __restrict__ attn, float* __restrict__ out_edge)
{
    extern __shared__ float sm[];
    float* sA  = sm;             // 128*260 = 33280
    float* sW  = sm + 33280;     // 2*256*20 = 10240
    float* sEt = sm + 43520;     // 128*66 = 8448
    float* sSc = sm + 51968;     // 512
    int*   sS  = (int*)(sm + 52480);   // 128
    int*   sD  = (int*)(sm + 52608);   // 128
    const unsigned sWu = smem_u32(sW);

    const int tid = threadIdx.x;
    const int e0 = blockIdx.x * 128;
    const int lane = tid & 31, wid = tid >> 5;
    const int wm = wid & 3, wn = wid >> 2;
    const int lq = lane >> 2, lc = lane & 3;

    if (tid < 128) {
        int e = min(e0 + tid, E - 1);
        sS[tid] = src[e]; sD[tid] = dst[e];
    }
    for (int i = tid; i < 128 * 32; i += 512) {
        int r = i >> 5, q = i & 31;
        float4 v = make_float4(0.f, 0.f, 0.f, 0.f);
        if (e0 + r < E) v = *(const float4*)(edge + (size_t)(e0 + r) * 128 + q * 4);
        v.x = to_tf32(v.x); v.y = to_tf32(v.y); v.z = to_tf32(v.z); v.w = to_tf32(v.w);
        *(float4*)(sA + r * 260 + q * 4) = v;
    }
    __syncthreads();

    // ---- stage Et: sEt = edge@W_et + b_et ----
    {
        float acc[2][2][4];
        gemm_stage<2>(sA, g_BtEt, 128, sW, sWu, tid, acc);
#pragma unroll
        for (int nf = 0; nf < 2; nf++) {
            int col = wn * 16 + nf * 8 + lc * 2;
            float2 bb = *(const float2*)(b_et + col);
#pragma unroll
            for (int mf = 0; mf < 2; mf++)
#pragma unroll
                for (int h = 0; h < 2; h++) {
                    int r = wm * 32 + mf * 16 + h * 8 + lq;
                    sEt[r * 66 + col]     = acc[mf][nf][h*2+0] + bb.x;
                    sEt[r * 66 + col + 1] = acc[mf][nf][h*2+1] + bb.y;
                }
        }
    }

    // ---- stage 0: sA = relu(edge@Wcomb + Pi[dst] + Pj[src] + A0_b) ----
    {
        float acc[2][8][4];
        gemm_stage<8>(sA, g_BtComb, 128, sW, sWu, tid, acc);
#pragma unroll
        for (int nf = 0; nf < 8; nf++) {
            int col = wn * 64 + nf * 8 + lc * 2;
            float2 bb = *(const float2*)(A0_b + col);
#pragma unroll
            for (int mf = 0; mf < 2; mf++)
#pragma unroll
                for (int h = 0; h < 2; h++) {
                    int r = wm * 32 + mf * 16 + h * 8 + lq;
                    int d = sD[r], s = sS[r];
                    float2 pi = *(const float2*)(g_Pi + (size_t)d * 256 + col);
                    float2 pj = *(const float2*)(g_Pj + (size_t)s * 256 + col);
                    sA[r * 260 + col]     = to_tf32(fmaxf(acc[mf][nf][h*2+0] + pi.x + pj.x + bb.x, 0.f));
                    sA[r * 260 + col + 1] = to_tf32(fmaxf(acc[mf][nf][h*2+1] + pi.y + pj.y + bb.y, 0.f));
                }
        }
    }
    __syncthreads();

    // ---- stage 1: sA = relu(sA@A1 + b1) ----
    {
        float acc[2][8][4];
        gemm_stage<8>(sA, g_BtA1, 256, sW, sWu, tid, acc);
#pragma unroll
        for (int nf = 0; nf < 8; nf++) {
            int col = wn * 64 + nf * 8 + lc * 2;
            float2 bb = *(const float2*)(A1_b + col);
#pragma unroll
            for (int mf = 0; mf < 2; mf++)
#pragma unroll
                for (int h = 0; h < 2; h++) {
                    int r = wm * 32 + mf * 16 + h * 8 + lq;
                    sA[r * 260 + col]     = to_tf32(fmaxf(acc[mf][nf][h*2+0] + bb.x, 0.f));
                    sA[r * 260 + col + 1] = to_tf32(fmaxf(acc[mf][nf][h*2+1] + bb.y, 0.f));
                }
        }
    }
    __syncthreads();

    // ---- stage 2: sA = relu(sA@A2 + b2), fused attention scores ----
    // wn strip is exactly one head (64 cols): head = wn.
    {
        float acc[2][8][4];
        gemm_stage<8>(sA, g_BtA2, 256, sW, sWu, tid, acc);
        float sp[2][2] = {{0.f, 0.f}, {0.f, 0.f}};
#pragma unroll
        for (int nf = 0; nf < 8; nf++) {
            int col = wn * 64 + nf * 8 + lc * 2;
            float2 bb = *(const float2*)(A2_b + col);
            float2 av = *(const float2*)(attn + col);
#pragma unroll
            for (int mf = 0; mf < 2; mf++)
#pragma unroll
                for (int h = 0; h < 2; h++) {
                    int r = wm * 32 + mf * 16 + h * 8 + lq;
                    float v0 = fmaxf(acc[mf][nf][h*2+0] + bb.x, 0.f);
                    float v1 = fmaxf(acc[mf][nf][h*2+1] + bb.y, 0.f);
                    sA[r * 260 + col]     = to_tf32(v0);
                    sA[r * 260 + col + 1] = to_tf32(v1);
                    sp[mf][h] += v0 * av.x + v1 * av.y;
                }
        }
#pragma unroll
        for (int mf = 0; mf < 2; mf++)
#pragma unroll
            for (int h = 0; h < 2; h++) {
                float v = sp[mf][h];
                v += __shfl_xor_sync(0xffffffffu, v, 1);
                v += __shfl_xor_sync(0xffffffffu, v, 2);
                if (lc == 0)
                    sSc[(wm * 32 + mf * 16 + h * 8 + lq) * 4 + wn] = v;
            }
    }
    __syncthreads();

    // ---- stage 3: sA(cols 0..63) = relu(sA@Em0 + b) ----
    {
        float acc[2][2][4];
        gemm_stage<2>(sA, g_BtEm0, 256, sW, sWu, tid, acc);
#pragma unroll
        for (int nf = 0; nf < 2; nf++) {
            int col = wn * 16 + nf * 8 + lc * 2;
            float2 bb = *(const float2*)(Em0_b + col);
#pragma unroll
            for (int mf = 0; mf < 2; mf++)
#pragma unroll
                for (int h = 0; h < 2; h++) {
                    int r = wm * 32 + mf * 16 + h * 8 + lq;
                    sA[r * 260 + col]     = to_tf32(fmaxf(acc[mf][nf][h*2+0] + bb.x, 0.f));
                    sA[r * 260 + col + 1] = to_tf32(fmaxf(acc[mf][nf][h*2+1] + bb.y, 0.f));
                }
        }
    }
    __syncthreads();

    // ---- stage 4: sA(cols 0..63) = relu(sA@Em1 + b) ----
    {
        float acc[2][2][4];
        gemm_stage<2>(sA, g_BtEm1, 64, sW, sWu, tid, acc);
#pragma unroll
        for (int nf = 0; nf < 2; nf++) {
            int col = wn * 16 + nf * 8 + lc * 2;
            float2 bb = *(const float2*)(Em1_b + col);
#pragma unroll
            for (int mf = 0; mf < 2; mf++)
#pragma unroll
                for (int h = 0; h < 2; h++) {
                    int r = wm * 32 + mf * 16 + h * 8 + lq;
                    sA[r * 260 + col]     = to_tf32(fmaxf(acc[mf][nf][h*2+0] + bb.x, 0.f));
                    sA[r * 260 + col + 1] = to_tf32(fmaxf(acc[mf][nf][h*2+1] + bb.y, 0.f));
                }
        }
    }
    __syncthreads();

    // ---- stage 5: out_edge = relu(sA@Em2 + b) + Et ----
    {
        float acc[2][2][4];
        gemm_stage<2>(sA, g_BtEm2, 64, sW, sWu, tid, acc);
#pragma unroll
        for (int nf = 0; nf < 2; nf++) {
            int col = wn * 16 + nf * 8 + lc * 2;
            float2 bb = *(const float2*)(Em2_b + col);
#pragma unroll
            for (int mf = 0; mf < 2; mf++)
#pragma unroll
                for (int h = 0; h < 2; h++) {
                    int r = wm * 32 + mf * 16 + h * 8 + lq;
                    if (e0 + r < E) {
                        float2 o;
                        o.x = fmaxf(acc[mf][nf][h*2+0] + bb.x, 0.f) + sEt[r * 66 + col];
                        o.y = fmaxf(acc[mf][nf][h*2+1] + bb.y, 0.f) + sEt[r * 66 + col + 1];
                        *(float2*)(out_edge + (size_t)(e0 + r) * 64 + col) = o;
                    }
                }
        }
    }
    __syncthreads();

    // ---- scores + segment max + degree ----
    {
        int r = tid >> 2, h = tid & 3;
        if (e0 + r < E) {
            float v = sSc[tid];
            g_scores[(size_t)(e0 + r) * 4 + h] = v;
            atomicMaxFloat(&g_smax[(size_t)sD[r] * 4 + h], v);
        }
    }
    if (tid < 128 && e0 + tid < E && sS[tid] != sD[tid])
        atomicAdd(&g_deg[sS[tid]], 1.0f);
}

// ---------------- tf32 warp-MMA GEMM body (node-level, 256 thr, row-major Bt) ----------------
static __device__ __forceinline__ void mma128_body(
    const float* __restrict__ A, const float* __restrict__ Bt,
    float* __restrict__ C, int M, int K, int ldc, int m0, int n0)
{
    __shared__ float As[128][20];
    __shared__ float Bs[128][20];

    const int tid = threadIdx.x;
    const int lane = tid & 31, wid = tid >> 5;
    const int wm = wid & 3, wn = wid >> 2;
    const int lq = lane >> 2;
    const int lc = lane & 3;

    float acc[2][8][4];
#pragma unroll
    for (int i = 0; i < 2; i++)
#pragma unroll
        for (int j = 0; j < 8; j++)
#pragma unroll
            for (int q = 0; q < 4; q++) acc[i][j][q] = 0.0f;

    for (int k0 = 0; k0 < K; k0 += 16) {
#pragma unroll
        for (int i = tid; i < 512; i += 256) {
            int m = i >> 2, q = i & 3;
            float4 v = make_float4(0.f, 0.f, 0.f, 0.f);
            int row = m0 + m;
            if (row < M) v = *reinterpret_cast<const float4*>(A + (size_t)row * K + k0 + q * 4);
            v.x = to_tf32(v.x); v.y = to_tf32(v.y); v.z = to_tf32(v.z); v.w = to_tf32(v.w);
            *reinterpret_cast<float4*>(&As[m][q * 4]) = v;
        }
#pragma unroll
        for (int i = tid; i < 512; i += 256) {
            int n = i >> 2, q = i & 3;
            float4 v = *reinterpret_cast<const float4*>(Bt + (size_t)(n0 + n) * K + k0 + q * 4);
            *reinterpret_cast<float4*>(&Bs[n][q * 4]) = v;
        }
        __syncthreads();

#pragma unroll
        for (int kk = 0; kk < 16; kk += 8) {
            unsigned a[2][4];
#pragma unroll
            for (int mf = 0; mf < 2; mf++) {
                int m = wm * 32 + mf * 16 + lq;
                a[mf][0] = __float_as_uint(As[m][kk + lc]);
                a[mf][1] = __float_as_uint(As[m + 8][kk + lc]);
                a[mf][2] = __float_as_uint(As[m][kk + 4 + lc]);
                a[mf][3] = __float_as_uint(As[m + 8][kk + 4 + lc]);
            }
            unsigned b[8][2];
#pragma unroll
            for (int nf = 0; nf < 8; nf++) {
                int n = wn * 64 + nf * 8 + lq;
                b[nf][0] = __float_as_uint(Bs[n][kk + lc]);
                b[nf][1] = __float_as_uint(Bs[n][kk + 4 + lc]);
            }
#pragma unroll
            for (int mf = 0; mf < 2; mf++)
#pragma unroll
                for (int nf = 0; nf < 8; nf++)
                    mma_tf32(acc[mf][nf], a[mf], b[nf]);
        }
        __syncthreads();
    }

#pragma unroll
    for (int mf = 0; mf < 2; mf++) {
#pragma unroll
        for (int nf = 0; nf < 8; nf++) {
            int row = m0 + wm * 32 + mf * 16 + lq;
            int col = n0 + wn * 64 + nf * 8 + lc * 2;
            float2 v0 = make_float2(acc[mf][nf][0], acc[mf][nf][1]);
            float2 v1 = make_float2(acc[mf][nf][2], acc[mf][nf][3]);
            if (row < M)
                *reinterpret_cast<float2*>(C + (size_t)row * ldc + col) = v0;
            if (row + 8 < M)
                *reinterpret_cast<float2*>(C + (size_t)(row + 8) * ldc + col) = v1;
        }
    }
}

__global__ void __launch_bounds__(256)
mma_node3(const float* __restrict__ A,
          const float* __restrict__ B0, const float* __restrict__ B1, const float* __restrict__ B2,
          float* __restrict__ C0, float* __restrict__ C1, float* __restrict__ C2, int M)
{
    int z = blockIdx.z;
    const float* Bt = (z == 0) ? B0 : (z == 1) ? B1 : B2;
    float* C = (z == 0) ? C0 : (z == 1) ? C1 : C2;
    mma128_body(A, Bt, C, M, 256, 256, blockIdx.x * 128, blockIdx.y * 128);
}

// ---------------- prep: folds (transposed row-major out) + weight transposes ----------------
struct PrepTable {
    const float* W[7];
    float* Bt[7];
    int K[7];
    int Nd[7];
};
__global__ void __launch_bounds__(256)
prep(const float* __restrict__ W_nj, const float* __restrict__ W_eij,
     const float* __restrict__ W_ni, const float* __restrict__ A0_W, PrepTable tab)
{
    int z = blockIdx.z;
    if (z >= 3) {
        int s = z - 3;
        const float* W = tab.W[s];
        float* Bt = tab.Bt[s];
        int K = tab.K[s], Nd = tab.Nd[s];
        int total = K * Nd;
        int bid = blockIdx.y * 2 + blockIdx.x;
        for (int i = bid * 256 + threadIdx.x; i < total; i += 4 * 256) {
            int k = i / Nd, n = i % Nd;
            Bt[(size_t)n * K + k] = to_tf32(W[i]);
        }
        return;
    }
    // fold GEMM with transposed tf32 output
    const float* A; const float* W; float* Bt; int M; int Kdim;
    if (z == 0)      { A = W_nj;  W = A0_W;             Bt = g_BtFold; M = 256; Kdim = 256; }
    else if (z == 1) { A = W_eij; W = A0_W + 256 * 256; Bt = g_BtComb; M = 128; Kdim = 128; }
    else             { A = W_ni;  W = A0_W + 512 * 256; Bt = g_BtPj;   M = 256; Kdim = 256; }
    const int m0 = blockIdx.x * 128;
    const int n0 = blockIdx.y * 128;
    if (m0 >= M) return;

    __shared__ float As[16][132];
    __shared__ float Ws[16][128];
    const int tid = threadIdx.x;
    const int tx = tid & 15, ty = tid >> 4;

    float acc[8][8];
#pragma unroll
    for (int i = 0; i < 8; i++)
#pragma unroll
        for (int j = 0; j < 8; j++) acc[i][j] = 0.0f;

    for (int k0 = 0; k0 < 256; k0 += 16) {
#pragma unroll
        for (int i = tid; i < 512; i += 256) {
            int m = i >> 2, k4 = i & 3;
            float4 v = *reinterpret_cast<const float4*>(A + (size_t)(m0 + m) * 256 + k0 + k4 * 4);
            As[k4 * 4 + 0][m] = v.x;
            As[k4 * 4 + 1][m] = v.y;
            As[k4 * 4 + 2][m] = v.z;
            As[k4 * 4 + 3][m] = v.w;
        }
#pragma unroll
        for (int i = tid; i < 512; i += 256) {
            int k = i >> 5, n4 = i & 31;
            *reinterpret_cast<float4*>(&Ws[k][n4 * 4]) =
                *reinterpret_cast<const float4*>(W + (size_t)(k0 + k) * 256 + n0 + n4 * 4);
        }
        __syncthreads();
#pragma unroll
        for (int k = 0; k < 16; k++) {
            float a[8], b[8];
#pragma unroll
            for (int i = 0; i < 8; i++) a[i] = As[k][ty * 8 + i];
#pragma unroll
            for (int j = 0; j < 8; j++) b[j] = Ws[k][tx * 8 + j];
#pragma unroll
            for (int i = 0; i < 8; i++)
#pragma unroll
                for (int j = 0; j < 8; j++)
                    acc[i][j] = fmaf(a[i], b[j], acc[i][j]);
        }
        __syncthreads();
    }
#pragma unroll
    for (int i = 0; i < 8; i++) {
        int krow = m0 + ty * 8 + i;
#pragma unroll
        for (int j = 0; j < 8; j++) {
            int ncol = n0 + tx * 8 + j;
            Bt[(size_t)ncol * Kdim + krow] = to_tf32(acc[i][j]);
        }
    }
}

// ---------------- generic tiled fp32 SGEMM ----------------
template<int BM, int BN, int BK, int TM, int TN, bool RELU, bool BIAS, bool RES>
__global__ void __launch_bounds__((BM / TM) * (BN / TN))
sgemm(const float* __restrict__ A, int lda,
      const float* __restrict__ W,
      const float* __restrict__ bias,
      const float* __restrict__ res, int ldres,
      float* __restrict__ C, int ldc,
      int M, int N, int K)
{
    constexpr int NT = (BM / TM) * (BN / TN);
    __shared__ float As[BK][BM + 4];
    __shared__ float Ws[BK][BN];

    const int tid = threadIdx.x;
    const int tx = tid % (BN / TN);
    const int ty = tid / (BN / TN);
    const int m0 = blockIdx.x * BM;
    const int n0 = blockIdx.y * BN;

    float acc[TM][TN];
#pragma unroll
    for (int i = 0; i < TM; i++)
#pragma unroll
        for (int j = 0; j < TN; j++) acc[i][j] = 0.0f;

    for (int k0 = 0; k0 < K; k0 += BK) {
#pragma unroll
        for (int i = tid; i < BM * BK / 4; i += NT) {
            int m  = i / (BK / 4);
            int k4 = i % (BK / 4);
            float4 v = make_float4(0.f, 0.f, 0.f, 0.f);
            int row = m0 + m;
            if (row < M)
                v = *reinterpret_cast<const float4*>(A + (size_t)row * lda + k0 + k4 * 4);
            As[k4 * 4 + 0][m] = v.x;
            As[k4 * 4 + 1][m] = v.y;
            As[k4 * 4 + 2][m] = v.z;
            As[k4 * 4 + 3][m] = v.w;
        }
#pragma unroll
        for (int i = tid; i < BK * BN / 4; i += NT) {
            int k  = i / (BN / 4);
            int n4 = i % (BN / 4);
            *reinterpret_cast<float4*>(&Ws[k][n4 * 4]) =
                *reinterpret_cast<const float4*>(W + (size_t)(k0 + k) * N + n0 + n4 * 4);
        }
        __syncthreads();

#pragma unroll
        for (int k = 0; k < BK; k++) {
            float a[TM], b[TN];
#pragma unroll
            for (int i = 0; i < TM; i++) a[i] = As[k][ty * TM + i];
#pragma unroll
            for (int j = 0; j < TN; j++) b[j] = Ws[k][tx * TN + j];
#pragma unroll
            for (int i = 0; i < TM; i++)
#pragma unroll
                for (int j = 0; j < TN; j++)
                    acc[i][j] = fmaf(a[i], b[j], acc[i][j]);
        }
        __syncthreads();
    }

#pragma unroll
    for (int i = 0; i < TM; i++) {
        int row = m0 + ty * TM + i;
        if (row >= M) continue;
#pragma unroll
        for (int j = 0; j < TN; j++) {
            int col = n0 + tx * TN + j;
            float v = acc[i][j];
            if (BIAS) v += bias[col];
            if (RELU) v = fmaxf(v, 0.0f);
            if (RES)  v += res[(size_t)row * ldres + col];
            C[(size_t)row * ldc + col] = v;
        }
    }
}

// ---------------- small kernels ----------------
__global__ void init_kernel(int N)
{
    int i = blockIdx.x * blockDim.x + threadIdx.x;
    if (i < N * 4) { g_smax[i] = -INFINITY; g_den[i] = 0.0f; }
    if (i < N * 256) g_agg[i] = 0.0f;
    if (i < N) g_deg[i] = 1.0f;
}

__global__ void ex_kernel(const int* __restrict__ dst, int E)
{
    int i = blockIdx.x * blockDim.x + threadIdx.x;
    if (i >= E * 4) return;
    int e = i >> 2, h = i & 3;
    int d = dst[e];
    float v = expf(g_scores[i] - g_smax[d * 4 + h]);
    g_ex[i] = v;
    atomicAdd(&g_den[d * 4 + h], v);
}

__global__ void agg_kernel(const int* __restrict__ src, const int* __restrict__ dst, int E,
                           const float* __restrict__ linW, float* __restrict__ attn_out)
{
    int idx = blockIdx.x * blockDim.x + threadIdx.x;
    int e = idx >> 6;
    int t = idx & 63;
    if (e >= E) return;
    int d = dst[e], s = src[e];
    int h = t >> 4;
    float alpha = g_ex[e * 4 + h] / g_den[(size_t)d * 4 + h];
    if (t == 0) {
        float aw = 0.0f;
#pragma unroll
        for (int hh = 0; hh < 4; hh++)
            aw += (g_ex[e * 4 + hh] / g_den[(size_t)d * 4 + hh]) * linW[hh];
        attn_out[e] = aw;
    }
    float4 xj = reinterpret_cast<const float4*>(g_Xni + (size_t)s * 256)[t];
    float4 m = make_float4(xj.x * alpha, xj.y * alpha, xj.z * alpha, xj.w * alpha);
    atomicAdd4(reinterpret_cast<float4*>(g_agg + (size_t)d * 256 + t * 4), m);
}

__global__ void outinit_kernel(const float* __restrict__ gcn_b, float* __restrict__ out, int N)
{
    int i = blockIdx.x * blockDim.x + threadIdx.x;
    if (i >= N * 64) return;
    int n = i >> 6;
    out[i] = gcn_b[i & 63] + g_xg[i] / g_deg[n];
}

__global__ void gcn_scatter_kernel(const int* __restrict__ src, const int* __restrict__ dst,
                                   int E, float* __restrict__ out)
{
    int idx = blockIdx.x * blockDim.x + threadIdx.x;
    int e = idx >> 4;
    int t = idx & 15;
    if (e >= E) return;
    int s = src[e], d = dst[e];
    if (s == d) return;
    float w = rsqrtf(g_deg[s]) * rsqrtf(g_deg[d]);
    float4 v = reinterpret_cast<const float4*>(g_xg + (size_t)s * 64)[t];
    float4 m = make_float4(v.x * w, v.y * w, v.z * w, v.w * w);
    atomicAdd4(reinterpret_cast<float4*>(out + (size_t)d * 64 + t * 4), m);
}

// ---------------- launch ----------------
extern "C" void kernel_launch(void* const* d_in, const int* in_sizes, int n_in,
                              void* d_out, int out_size)
{
    const float* node = (const float*)d_in[0];
    const float* edge = (const float*)d_in[1];
    const int*   ei   = (const int*)d_in[2];
    const float* W_ni = (const float*)d_in[3];
    const float* W_nj = (const float*)d_in[4];
    const float* W_eij= (const float*)d_in[5];
    const float* W_nt = (const float*)d_in[6];
    const float* b_nt = (const float*)d_in[7];
    const float* W_et = (const float*)d_in[8];
    const float* b_et = (const float*)d_in[9];
    const float* A0_W = (const float*)d_in[10];
    const float* A0_b = (const float*)d_in[11];
    const float* A1_W = (const float*)d_in[12];
    const float* A1_b = (const float*)d_in[13];
    const float* A2_W = (const float*)d_in[14];
    const float* A2_b = (const float*)d_in[15];
    const float* attn = (const float*)d_in[16];
    const float* Nm0_W= (const float*)d_in[17];
    const float* Nm0_b= (const float*)d_in[18];
    const float* Nm1_W= (const float*)d_in[19];
    const float* Nm1_b= (const float*)d_in[20];
    const float* Nm2_W= (const float*)d_in[21];
    const float* Nm2_b= (const float*)d_in[22];
    const float* Em0_W= (const float*)d_in[23];
    const float* Em0_b= (const float*)d_in[24];
    const float* Em1_W= (const float*)d_in[25];
    const float* Em1_b= (const float*)d_in[26];
    const float* Em2_W= (const float*)d_in[27];
    const float* Em2_b= (const float*)d_in[28];
    const float* linW = (const float*)d_in[29];
    const float* gcnW = (const float*)d_in[30];
    const float* gcnb = (const float*)d_in[31];

    const int N = in_sizes[0] / 256;
    const int E = in_sizes[2] / 2;
    const int* src = ei;
    const int* dst = ei + E;

    float* out      = (float*)d_out;
    float* out_node = out;
    float* out_edge = out + (size_t)N * 64;
    float* out_attn = out_edge + (size_t)E * 64;

    void* p;
    cudaGetSymbolAddress(&p, g_Xni);    float* pXni = (float*)p;
    cudaGetSymbolAddress(&p, g_Xnt);    float* pXnt = (float*)p;
    cudaGetSymbolAddress(&p, g_Pi);     float* pPi  = (float*)p;
    cudaGetSymbolAddress(&p, g_Pj);     float* pPj  = (float*)p;
    cudaGetSymbolAddress(&p, g_agg);    float* pAgg = (float*)p;
    cudaGetSymbolAddress(&p, g_NM0);    float* pNM0 = (float*)p;
    cudaGetSymbolAddress(&p, g_NM1);    float* pNM1 = (float*)p;
    cudaGetSymbolAddress(&p, g_nodeout); float* pNodeOut = (float*)p;
    cudaGetSymbolAddress(&p, g_xg);     float* pXg  = (float*)p;
    cudaGetSymbolAddress(&p, g_BtA1);   float* pBtA1 = (float*)p;
    cudaGetSymbolAddress(&p, g_BtA2);   float* pBtA2 = (float*)p;
    cudaGetSymbolAddress(&p, g_BtEm0);  float* pBtEm0 = (float*)p;
    cudaGetSymbolAddress(&p, g_BtEm1);  float* pBtEm1 = (float*)p;
    cudaGetSymbolAddress(&p, g_BtEm2);  float* pBtEm2 = (float*)p;
    cudaGetSymbolAddress(&p, g_BtEt);   float* pBtEt = (float*)p;
    cudaGetSymbolAddress(&p, g_BtNi);   float* pBtNi = (float*)p;
    cudaGetSymbolAddress(&p, g_BtFold); float* pBtFold = (float*)p;
    cudaGetSymbolAddress(&p, g_BtPj);   float* pBtPj = (float*)p;

    const int TPB = 256;
    const int MT_N = (N + 127) / 128;
    const int ET = (E + 127) / 128;
    const int FUSED_SMEM = 52736 * 4;             // 206 KB
    cudaFuncSetAttribute(edge_fused, cudaFuncAttributeMaxDynamicSharedMemorySize, FUSED_SMEM);

    // #1 init
    init_kernel<<<(N * 256 + TPB - 1) / TPB, TPB>>>(N);

    // #2 prep: folds + transposes (all row-major [N,K] tf32)
    {
        PrepTable tab;
        tab.W[0] = A1_W;  tab.Bt[0] = pBtA1;  tab.K[0] = 256; tab.Nd[0] = 256;
        tab.W[1] = A2_W;  tab.Bt[1] = pBtA2;  tab.K[1] = 256; tab.Nd[1] = 256;
        tab.W[2] = Em0_W; tab.Bt[2] = pBtEm0; tab.K[2] = 256; tab.Nd[2] = 64;
        tab.W[3] = Em1_W; tab.Bt[3] = pBtEm1; tab.K[3] = 64;  tab.Nd[3] = 64;
        tab.W[4] = Em2_W; tab.Bt[4] = pBtEm2; tab.K[4] = 64;  tab.Nd[4] = 64;
        tab.W[5] = W_et;  tab.Bt[5] = pBtEt;  tab.K[5] = 128; tab.Nd[5] = 64;
        tab.W[6] = W_ni;  tab.Bt[6] = pBtNi;  tab.K[6] = 256; tab.Nd[6] = 256;
        dim3 g(2, 2, 10);
        prep<<<g, 256>>>(W_nj, W_eij, W_ni, A0_W, tab);
    }

    // #3 node projections batched: Xni / Pi / Pj
    {
        dim3 g(MT_N, 2, 3);
        mma_node3<<<g, 256>>>(node, pBtNi, pBtFold, pBtPj, pXni, pPi, pPj, N);
    }

    // #4 fused edge chain (profiled position)
    edge_fused<<<ET, 512, FUSED_SMEM>>>(edge, src, dst, E, A0_b, A1_b, A2_b,
                                        Em0_b, Em1_b, Em2_b, b_et, attn, out_edge);

    // #5 Xnt (fp32)
    {
        dim3 g(MT_N, 1);
        sgemm<128,64,16,8,4,false,true,false><<<g, 256>>>(node, 256, W_nt, b_nt, nullptr, 0, pXnt, 64, N, 64, 256);
    }

    // #6 softmax denominators
    ex_kernel<<<((size_t)E * 4 + TPB - 1) / TPB, TPB>>>(dst, E);

    // #7 message aggregation + attn weights
    agg_kernel<<<((size_t)E * 64 + TPB - 1) / TPB, TPB>>>(src, dst, E, linW, out_attn);

    // #8-11 node MLP + xg
    {
        dim3 g(MT_N, 1);
        sgemm<128,64,16,8,4,true,true,false><<<g, 256>>>(pAgg, 256, Nm0_W, Nm0_b, nullptr, 0, pNM0, 64, N, 64, 256);
        sgemm<128,64,16,8,4,true,true,false><<<g, 256>>>(pNM0, 64, Nm1_W, Nm1_b, nullptr, 0, pNM1, 64, N, 64, 64);
        sgemm<128,64,16,8,4,true,true,true><<<g, 256>>>(pNM1, 64, Nm2_W, Nm2_b, pXnt, 64, pNodeOut, 64, N, 64, 64);
        sgemm<128,64,16,8,4,false,false,false><<<g, 256>>>(pNodeOut, 64, gcnW, nullptr, nullptr, 0, pXg, 64, N, 64, 64);
    }

    // #12 out_node init
    outinit_kernel<<<(N * 64 + TPB - 1) / TPB, TPB>>>(gcnb, out_node, N);

    // #13 GCN scatter
    gcn_scatter_kernel<<<((size_t)E * 16 + TPB - 1) / TPB, TPB>>>(src, dst, E, out_node);
}